// round 11
// baseline (speedup 1.0000x reference)
#include <cuda_runtime.h>
#include <cuda_bf16.h>

// IoUMetricLoss: pred_label fp32 [8,19,512,1024], label int32 [8,512,1024]
// out: scalar fp32 = 1 - nanmean(IoU per class), all-NaN -> 0.5
//
// R11: split kernels (R10 showed pure-stream A hits 6.5 TB/s vs 5.77
// fused). A unchanged: streaming argmax -> packed uint8 indices.
// B fixed: R10's B had 64B-stride label loads (16 lines/LDG, 25% sector
// efficiency -> 16.8us latency-bound). Now 4 px/thread, fully coalesced
// label int4 + idx uint loads, 4 CM smem atomics/thread, fused last-block
// finalize + state reset.

#define NUM_CLASSES 19
#define CM_BINS (NUM_CLASSES * NUM_CLASSES)   // 361
#define HW_SHIFT 19                  // 512*1024 = 2^19
#define HW (1 << HW_SHIFT)
#define TOTAL_PIX (8 * HW)           // 4194304
#define VEC_GROUPS (TOTAL_PIX / 4)   // 1048576
#define A_BLOCK 256
#define A_GRID (VEC_GROUPS / A_BLOCK)          // 4096
#define B_BLOCK 256
#define B_GRID (VEC_GROUPS / B_BLOCK)          // 4096
#define B_WARPS (B_BLOCK / 32)

// Scratch + accumulators (no cudaMalloc allowed). g_idx: 4 packed uint8
// argmax indices per vec-group. g_cm statically zero; B's finalizer
// re-zeros it so every graph replay sees clean state.
__device__ unsigned int g_idx[VEC_GROUPS];     // 4 MB scratch
__device__ unsigned int g_cm[CM_BINS];
__device__ unsigned int g_done;

__device__ __forceinline__ void amax_step(float v, float& bv, int& bi, int c) {
    float m = fmaxf(bv, v);
    bi = (v > bv) ? c : bi;
    bv = m;
}

// ---------- Kernel A: pure streaming argmax (R10-proven, 6.5 TB/s) ----------
__global__ void __launch_bounds__(A_BLOCK)
iou_argmax_kernel(const float* __restrict__ pred) {
    const unsigned t  = blockIdx.x * A_BLOCK + threadIdx.x;  // vec-group id
    const unsigned P  = t << 2;
    const unsigned b  = P >> HW_SHIFT;
    const unsigned hw = P & (HW - 1);

    const float* base = pred + ((size_t)b * NUM_CLASSES << HW_SHIFT) + hw;

    float4 bv = __ldcs((const float4*)base);
    int i0 = 0, i1 = 0, i2 = 0, i3 = 0;
    #pragma unroll
    for (int c = 1; c < NUM_CLASSES; c++) {
        float4 v = __ldcs((const float4*)(base + ((size_t)c << HW_SHIFT)));
        amax_step(v.x, bv.x, i0, c);
        amax_step(v.y, bv.y, i1, c);
        amax_step(v.z, bv.z, i2, c);
        amax_step(v.w, bv.w, i3, c);
    }
    // default-cached store: B reads this right after -> mostly L2-hot
    g_idx[t] = (unsigned)i0 | ((unsigned)i1 << 8) |
               ((unsigned)i2 << 16) | ((unsigned)i3 << 24);
}

// ---------- Kernel B: coalesced histogram + fused finalize ----------
__global__ void __launch_bounds__(B_BLOCK)
iou_hist_kernel(const int* __restrict__ label, float* __restrict__ out) {
    __shared__ unsigned int s_cm[B_WARPS][CM_BINS];
    __shared__ int          s_is_last;
    __shared__ float        s_loss;

    const int tid  = threadIdx.x;
    const int warp = tid >> 5;
    const int lane = tid & 31;

    #pragma unroll
    for (int i = lane; i < CM_BINS; i += 32)
        s_cm[warp][i] = 0u;
    __syncwarp();

    // one vec-group (4 px) per thread: all loads fully coalesced
    const unsigned t = blockIdx.x * B_BLOCK + tid;      // vec-group id
    unsigned pk = g_idx[t];                             // 4B/lane, coalesced
    int4 lv = __ldcs((const int4*)(label + ((size_t)t << 2)));  // 16B/lane

    int p0 = pk & 0xFF, p1 = (pk >> 8) & 0xFF;
    int p2 = (pk >> 16) & 0xFF, p3 = (pk >> 24) & 0xFF;
    if (lv.x >= 0) atomicAdd(&s_cm[warp][lv.x * NUM_CLASSES + p0], 1u);
    if (lv.y >= 0) atomicAdd(&s_cm[warp][lv.y * NUM_CLASSES + p1], 1u);
    if (lv.z >= 0) atomicAdd(&s_cm[warp][lv.z * NUM_CLASSES + p2], 1u);
    if (lv.w >= 0) atomicAdd(&s_cm[warp][lv.w * NUM_CLASSES + p3], 1u);
    __syncthreads();

    // block reduce -> global CM (skip empty bins)
    for (int bin = tid; bin < CM_BINS; bin += B_BLOCK) {
        unsigned s = 0u;
        #pragma unroll
        for (int w = 0; w < B_WARPS; w++) s += s_cm[w][bin];
        if (s) atomicAdd(&g_cm[bin], s);
    }
    __syncthreads();

    if (tid == 0) {
        __threadfence();
        unsigned prev = atomicAdd(&g_done, 1u);
        s_is_last = (prev == gridDim.x - 1);
    }
    __syncthreads();
    if (!s_is_last) return;

    if (tid < 32) {
        const int c = tid;
        float iou_sum = 0.0f;
        int   valid   = 0;
        if (c < NUM_CLASSES) {
            unsigned long long lab = 0, pr = 0;
            #pragma unroll
            for (int k = 0; k < NUM_CLASSES; k++) {
                lab += g_cm[c * NUM_CLASSES + k];   // row sum: area_label
                pr  += g_cm[k * NUM_CLASSES + c];   // col sum: area_pred
            }
            unsigned long long inter = g_cm[c * NUM_CLASSES + c];
            unsigned long long uni   = lab + pr - inter;
            if (uni > 0ULL) {
                iou_sum = (float)inter / (float)uni;
                valid   = 1;
            }
            // uni == 0 -> 0/0 = NaN in reference, excluded by nanmean
        }
        #pragma unroll
        for (int o = 16; o > 0; o >>= 1) {
            iou_sum += __shfl_down_sync(0xFFFFFFFFu, iou_sum, o);
            valid   += __shfl_down_sync(0xFFFFFFFFu, valid, o);
        }
        if (c == 0)
            s_loss = (valid > 0) ? (1.0f - iou_sum / (float)valid) : 0.5f;
    }
    __syncthreads();
    // reset global state for the next graph replay, then emit
    for (int bin = tid; bin < CM_BINS; bin += B_BLOCK)
        g_cm[bin] = 0u;
    if (tid == 0) {
        g_done = 0u;
        *out = s_loss;
    }
}

extern "C" void kernel_launch(void* const* d_in, const int* in_sizes, int n_in,
                              void* d_out, int out_size) {
    // pred = 79,691,776 elems; label = 4,194,304 (resolve by size).
    const float* pred;
    const int*   label;
    if (in_sizes[0] >= in_sizes[1]) {
        pred  = (const float*)d_in[0];
        label = (const int*)d_in[1];
    } else {
        pred  = (const float*)d_in[1];
        label = (const int*)d_in[0];
    }
    float* out = (float*)d_out;

    iou_argmax_kernel<<<A_GRID, A_BLOCK>>>(pred);
    iou_hist_kernel<<<B_GRID, B_BLOCK>>>(label, out);
}

// round 12
// speedup vs baseline: 1.4571x; 1.4571x over previous
#include <cuda_runtime.h>
#include <cuda_bf16.h>

// IoUMetricLoss: pred_label fp32 [8,19,512,1024], label int32 [8,512,1024]
// out: scalar fp32 = 1 - nanmean(IoU per class), all-NaN -> 0.5
//
// R12: split kernels. A (unchanged, 6.5 TB/s): streaming argmax -> packed
// uint8 indices. B rebuilt: R11 showed B's cost scales with BLOCK COUNT,
// not bytes -> per-address L2 atomic serialization of the 361-bin epilogue
// (4096 ops/address x ~27 cyc ~ 44us). Now 296 blocks (2/SM) grid-stride:
// 296 ops/address ~ 4us, main loop coalesced at ~14 vec-groups/thread.

#define NUM_CLASSES 19
#define CM_BINS (NUM_CLASSES * NUM_CLASSES)   // 361
#define HW_SHIFT 19                  // 512*1024 = 2^19
#define HW (1 << HW_SHIFT)
#define TOTAL_PIX (8 * HW)           // 4194304
#define VEC_GROUPS (TOTAL_PIX / 4)   // 1048576
#define A_BLOCK 256
#define A_GRID (VEC_GROUPS / A_BLOCK)          // 4096
#define B_BLOCK 256
#define B_GRID 296                   // 2 per SM -> epilogue contention 296/addr
#define B_WARPS (B_BLOCK / 32)

// Scratch + accumulators (no cudaMalloc allowed). g_idx: 4 packed uint8
// argmax indices per vec-group. g_cm statically zero; B's finalizer
// re-zeros it so every graph replay sees clean state.
__device__ unsigned int g_idx[VEC_GROUPS];     // 4 MB scratch
__device__ unsigned int g_cm[CM_BINS];
__device__ unsigned int g_done;

__device__ __forceinline__ void amax_step(float v, float& bv, int& bi, int c) {
    float m = fmaxf(bv, v);
    bi = (v > bv) ? c : bi;
    bv = m;
}

// ---------- Kernel A: pure streaming argmax (R10-proven, 6.5 TB/s) ----------
__global__ void __launch_bounds__(A_BLOCK)
iou_argmax_kernel(const float* __restrict__ pred) {
    const unsigned t  = blockIdx.x * A_BLOCK + threadIdx.x;  // vec-group id
    const unsigned P  = t << 2;
    const unsigned b  = P >> HW_SHIFT;
    const unsigned hw = P & (HW - 1);

    const float* base = pred + ((size_t)b * NUM_CLASSES << HW_SHIFT) + hw;

    float4 bv = __ldcs((const float4*)base);
    int i0 = 0, i1 = 0, i2 = 0, i3 = 0;
    #pragma unroll
    for (int c = 1; c < NUM_CLASSES; c++) {
        float4 v = __ldcs((const float4*)(base + ((size_t)c << HW_SHIFT)));
        amax_step(v.x, bv.x, i0, c);
        amax_step(v.y, bv.y, i1, c);
        amax_step(v.z, bv.z, i2, c);
        amax_step(v.w, bv.w, i3, c);
    }
    // default-cached store: B reads this right after -> mostly L2-hot
    g_idx[t] = (unsigned)i0 | ((unsigned)i1 << 8) |
               ((unsigned)i2 << 16) | ((unsigned)i3 << 24);
}

// ---------- Kernel B: grid-stride histogram + fused finalize ----------
__global__ void __launch_bounds__(B_BLOCK)
iou_hist_kernel(const int* __restrict__ label, float* __restrict__ out) {
    __shared__ unsigned int s_cm[B_WARPS][CM_BINS];
    __shared__ int          s_is_last;
    __shared__ float        s_loss;

    const int tid  = threadIdx.x;
    const int warp = tid >> 5;
    const int lane = tid & 31;

    #pragma unroll
    for (int i = lane; i < CM_BINS; i += 32)
        s_cm[warp][i] = 0u;
    __syncwarp();

    // grid-stride over vec-groups: all loads fully coalesced per iteration
    const unsigned stride = B_GRID * B_BLOCK;          // 75776
    for (unsigned t = blockIdx.x * B_BLOCK + tid; t < VEC_GROUPS; t += stride) {
        unsigned pk = g_idx[t];                             // 4B/lane
        int4 lv = __ldcs((const int4*)(label + ((size_t)t << 2)));  // 16B/lane

        int p0 = pk & 0xFF, p1 = (pk >> 8) & 0xFF;
        int p2 = (pk >> 16) & 0xFF, p3 = (pk >> 24) & 0xFF;
        if (lv.x >= 0) atomicAdd(&s_cm[warp][lv.x * NUM_CLASSES + p0], 1u);
        if (lv.y >= 0) atomicAdd(&s_cm[warp][lv.y * NUM_CLASSES + p1], 1u);
        if (lv.z >= 0) atomicAdd(&s_cm[warp][lv.z * NUM_CLASSES + p2], 1u);
        if (lv.w >= 0) atomicAdd(&s_cm[warp][lv.w * NUM_CLASSES + p3], 1u);
    }
    __syncthreads();

    // block reduce -> global CM: only 296 contributors per address
    for (int bin = tid; bin < CM_BINS; bin += B_BLOCK) {
        unsigned s = 0u;
        #pragma unroll
        for (int w = 0; w < B_WARPS; w++) s += s_cm[w][bin];
        if (s) atomicAdd(&g_cm[bin], s);
    }
    __syncthreads();

    if (tid == 0) {
        __threadfence();
        unsigned prev = atomicAdd(&g_done, 1u);
        s_is_last = (prev == gridDim.x - 1);
    }
    __syncthreads();
    if (!s_is_last) return;

    if (tid < 32) {
        const int c = tid;
        float iou_sum = 0.0f;
        int   valid   = 0;
        if (c < NUM_CLASSES) {
            unsigned long long lab = 0, pr = 0;
            #pragma unroll
            for (int k = 0; k < NUM_CLASSES; k++) {
                lab += g_cm[c * NUM_CLASSES + k];   // row sum: area_label
                pr  += g_cm[k * NUM_CLASSES + c];   // col sum: area_pred
            }
            unsigned long long inter = g_cm[c * NUM_CLASSES + c];
            unsigned long long uni   = lab + pr - inter;
            if (uni > 0ULL) {
                iou_sum = (float)inter / (float)uni;
                valid   = 1;
            }
            // uni == 0 -> 0/0 = NaN in reference, excluded by nanmean
        }
        #pragma unroll
        for (int o = 16; o > 0; o >>= 1) {
            iou_sum += __shfl_down_sync(0xFFFFFFFFu, iou_sum, o);
            valid   += __shfl_down_sync(0xFFFFFFFFu, valid, o);
        }
        if (c == 0)
            s_loss = (valid > 0) ? (1.0f - iou_sum / (float)valid) : 0.5f;
    }
    __syncthreads();
    // reset global state for the next graph replay, then emit
    for (int bin = tid; bin < CM_BINS; bin += B_BLOCK)
        g_cm[bin] = 0u;
    if (tid == 0) {
        g_done = 0u;
        *out = s_loss;
    }
}

extern "C" void kernel_launch(void* const* d_in, const int* in_sizes, int n_in,
                              void* d_out, int out_size) {
    // pred = 79,691,776 elems; label = 4,194,304 (resolve by size).
    const float* pred;
    const int*   label;
    if (in_sizes[0] >= in_sizes[1]) {
        pred  = (const float*)d_in[0];
        label = (const int*)d_in[1];
    } else {
        pred  = (const float*)d_in[1];
        label = (const int*)d_in[0];
    }
    float* out = (float*)d_out;

    iou_argmax_kernel<<<A_GRID, A_BLOCK>>>(pred);
    iou_hist_kernel<<<B_GRID, B_BLOCK>>>(label, out);
}

// round 13
// speedup vs baseline: 1.6054x; 1.1018x over previous
#include <cuda_runtime.h>
#include <cuda_bf16.h>

// IoUMetricLoss: pred_label fp32 [8,19,512,1024], label int32 [8,512,1024]
// out: scalar fp32 = 1 - nanmean(IoU per class), all-NaN -> 0.5
//
// R13: split kernels. A (unchanged, 6.5 TB/s proven): streaming argmax ->
// packed uint8 indices. B: R12 fixed the epilogue (296 contributors/addr)
// but left the main loop at occ=24% (2 CTA/SM x 8 warps). Now 296 blocks
// x 1024 threads = 64 warps/SM (100% occ) with the SAME 296-way epilogue
// contention. 32 per-warp 361-bin smem hists (46 KB/CTA).

#define NUM_CLASSES 19
#define CM_BINS (NUM_CLASSES * NUM_CLASSES)   // 361
#define HW_SHIFT 19                  // 512*1024 = 2^19
#define HW (1 << HW_SHIFT)
#define TOTAL_PIX (8 * HW)           // 4194304
#define VEC_GROUPS (TOTAL_PIX / 4)   // 1048576
#define A_BLOCK 256
#define A_GRID (VEC_GROUPS / A_BLOCK)          // 4096
#define B_BLOCK 1024
#define B_GRID 296                   // 2 CTA/SM; epilogue contention 296/addr
#define B_WARPS (B_BLOCK / 32)       // 32

// Scratch + accumulators (no cudaMalloc allowed). g_idx: 4 packed uint8
// argmax indices per vec-group. g_cm statically zero; B's finalizer
// re-zeros it so every graph replay sees clean state.
__device__ unsigned int g_idx[VEC_GROUPS];     // 4 MB scratch
__device__ unsigned int g_cm[CM_BINS];
__device__ unsigned int g_done;

__device__ __forceinline__ void amax_step(float v, float& bv, int& bi, int c) {
    float m = fmaxf(bv, v);
    bi = (v > bv) ? c : bi;
    bv = m;
}

// ---------- Kernel A: pure streaming argmax (R10-proven, 6.5 TB/s) ----------
__global__ void __launch_bounds__(A_BLOCK)
iou_argmax_kernel(const float* __restrict__ pred) {
    const unsigned t  = blockIdx.x * A_BLOCK + threadIdx.x;  // vec-group id
    const unsigned P  = t << 2;
    const unsigned b  = P >> HW_SHIFT;
    const unsigned hw = P & (HW - 1);

    const float* base = pred + ((size_t)b * NUM_CLASSES << HW_SHIFT) + hw;

    float4 bv = __ldcs((const float4*)base);
    int i0 = 0, i1 = 0, i2 = 0, i3 = 0;
    #pragma unroll
    for (int c = 1; c < NUM_CLASSES; c++) {
        float4 v = __ldcs((const float4*)(base + ((size_t)c << HW_SHIFT)));
        amax_step(v.x, bv.x, i0, c);
        amax_step(v.y, bv.y, i1, c);
        amax_step(v.z, bv.z, i2, c);
        amax_step(v.w, bv.w, i3, c);
    }
    // default-cached store: B reads this right after -> mostly L2-hot
    g_idx[t] = (unsigned)i0 | ((unsigned)i1 << 8) |
               ((unsigned)i2 << 16) | ((unsigned)i3 << 24);
}

// ---------- Kernel B: fat-block histogram + fused finalize ----------
__global__ void __launch_bounds__(B_BLOCK)
iou_hist_kernel(const int* __restrict__ label, float* __restrict__ out) {
    __shared__ unsigned int s_cm[B_WARPS][CM_BINS];   // 46 KB
    __shared__ int          s_is_last;
    __shared__ float        s_loss;

    const int tid  = threadIdx.x;
    const int warp = tid >> 5;
    const int lane = tid & 31;

    #pragma unroll
    for (int i = lane; i < CM_BINS; i += 32)
        s_cm[warp][i] = 0u;
    __syncwarp();

    // grid-stride over vec-groups: all loads fully coalesced per iteration
    const unsigned stride = B_GRID * B_BLOCK;          // 303104
    for (unsigned t = blockIdx.x * B_BLOCK + tid; t < VEC_GROUPS; t += stride) {
        unsigned pk = g_idx[t];                             // 4B/lane
        int4 lv = __ldcs((const int4*)(label + ((size_t)t << 2)));  // 16B/lane

        int p0 = pk & 0xFF, p1 = (pk >> 8) & 0xFF;
        int p2 = (pk >> 16) & 0xFF, p3 = (pk >> 24) & 0xFF;
        if (lv.x >= 0) atomicAdd(&s_cm[warp][lv.x * NUM_CLASSES + p0], 1u);
        if (lv.y >= 0) atomicAdd(&s_cm[warp][lv.y * NUM_CLASSES + p1], 1u);
        if (lv.z >= 0) atomicAdd(&s_cm[warp][lv.z * NUM_CLASSES + p2], 1u);
        if (lv.w >= 0) atomicAdd(&s_cm[warp][lv.w * NUM_CLASSES + p3], 1u);
    }
    __syncthreads();

    // block reduce -> global CM: 296 contributors per address
    for (int bin = tid; bin < CM_BINS; bin += B_BLOCK) {
        unsigned s = 0u;
        #pragma unroll
        for (int w = 0; w < B_WARPS; w++) s += s_cm[w][bin];
        if (s) atomicAdd(&g_cm[bin], s);
    }
    __syncthreads();

    if (tid == 0) {
        __threadfence();
        unsigned prev = atomicAdd(&g_done, 1u);
        s_is_last = (prev == gridDim.x - 1);
    }
    __syncthreads();
    if (!s_is_last) return;

    if (tid < 32) {
        const int c = tid;
        float iou_sum = 0.0f;
        int   valid   = 0;
        if (c < NUM_CLASSES) {
            unsigned long long lab = 0, pr = 0;
            #pragma unroll
            for (int k = 0; k < NUM_CLASSES; k++) {
                lab += g_cm[c * NUM_CLASSES + k];   // row sum: area_label
                pr  += g_cm[k * NUM_CLASSES + c];   // col sum: area_pred
            }
            unsigned long long inter = g_cm[c * NUM_CLASSES + c];
            unsigned long long uni   = lab + pr - inter;
            if (uni > 0ULL) {
                iou_sum = (float)inter / (float)uni;
                valid   = 1;
            }
            // uni == 0 -> 0/0 = NaN in reference, excluded by nanmean
        }
        #pragma unroll
        for (int o = 16; o > 0; o >>= 1) {
            iou_sum += __shfl_down_sync(0xFFFFFFFFu, iou_sum, o);
            valid   += __shfl_down_sync(0xFFFFFFFFu, valid, o);
        }
        if (c == 0)
            s_loss = (valid > 0) ? (1.0f - iou_sum / (float)valid) : 0.5f;
    }
    __syncthreads();
    // reset global state for the next graph replay, then emit
    for (int bin = tid; bin < CM_BINS; bin += B_BLOCK)
        g_cm[bin] = 0u;
    if (tid == 0) {
        g_done = 0u;
        *out = s_loss;
    }
}

extern "C" void kernel_launch(void* const* d_in, const int* in_sizes, int n_in,
                              void* d_out, int out_size) {
    // pred = 79,691,776 elems; label = 4,194,304 (resolve by size).
    const float* pred;
    const int*   label;
    if (in_sizes[0] >= in_sizes[1]) {
        pred  = (const float*)d_in[0];
        label = (const int*)d_in[1];
    } else {
        pred  = (const float*)d_in[1];
        label = (const int*)d_in[0];
    }
    float* out = (float*)d_out;

    iou_argmax_kernel<<<A_GRID, A_BLOCK>>>(pred);
    iou_hist_kernel<<<B_GRID, B_BLOCK>>>(label, out);
}